// round 4
// baseline (speedup 1.0000x reference)
#include <cuda_runtime.h>
#include <math.h>

// ---------------------------------------------------------------------------
// fVSRN: PE(36) + trilinear grid sample(16) -> [52] -> 128 -> 128 -> 128 ->
// 128 -> 1, snake activation. fp32 block-tiled SGEMM chain with packed
// FFMA2 (fma.rn.f32x2, Blackwell sm_103a) inner loop. 128 points/block,
// 256 threads, 8x8 register micro-tiles held as 4x8 f32x2 pairs.
// Weight staging fully unrolled so all 16 LDG.128 front-batch (one L2
// round-trip exposed per layer instead of several).
// ---------------------------------------------------------------------------

#define PI_F 3.14159265358979323846f

// Transposed feature grid [D][H][W][C] so each corner gather is 64B contiguous.
// 64*64*64*16 floats = 16 MB static device scratch (allowed: __device__ global).
__device__ float g_gridT[64 * 64 * 64 * 16];

__global__ void grid_transpose_kernel(const float* __restrict__ g) {
    int i = blockIdx.x * blockDim.x + threadIdx.x;   // 0 .. 2^22-1
    int c = i & 15;
    int s = i >> 4;                                   // spatial (z*64+y)*64+x
    g_gridT[i] = g[c * 262144 + s];
}

// ---- packed f32x2 helpers (sm_103a FFMA2 path) ----------------------------
__device__ __forceinline__ unsigned long long pack2(float lo, float hi) {
    unsigned long long r;
    asm("mov.b64 %0, {%1, %2};" : "=l"(r) : "f"(lo), "f"(hi));
    return r;
}
__device__ __forceinline__ void unpack2(float& lo, float& hi,
                                        unsigned long long v) {
    asm("mov.b64 {%0, %1}, %2;" : "=f"(lo), "=f"(hi) : "l"(v));
}
__device__ __forceinline__ void ffma2(unsigned long long& d,
                                      unsigned long long a,
                                      unsigned long long b) {
    asm("fma.rn.f32x2 %0, %1, %2, %0;" : "+l"(d) : "l"(a), "l"(b));
}

// Swizzled SMEM layout: logical (row, col), 128 floats/row, XOR swizzle on
// float4 granularity so vector loads stay 16B-aligned and near-conflict-free.
__device__ __forceinline__ int swiz(int row, int col) {
    return row * 128 + ((((col >> 2) ^ row) & 31) << 2) + (col & 3);
}

// out[p][n] = snake( sum_k aT[k][p] * wT[k][n] + bias[n] )
// aT/wT are swizzled SMEM images; result written transposed (row=n) so it is
// directly the next layer's aT. Accumulators: 4x8 f32x2 pairs (pairs along p).
template <int K, bool SNAKE>
__device__ __forceinline__ void gemm_tile(const float* __restrict__ aT,
                                          const float* __restrict__ wT,
                                          const float* __restrict__ bias,
                                          float* __restrict__ outT,
                                          int tx, int ty) {
    unsigned long long acc[4][8];
#pragma unroll
    for (int i = 0; i < 4; ++i)
#pragma unroll
        for (int j = 0; j < 8; ++j) acc[i][j] = 0ull;

#pragma unroll 4
    for (int k = 0; k < K; ++k) {
        int s = k & 31;
        const float4* ar = reinterpret_cast<const float4*>(aT + k * 128);
        const float4* wr = reinterpret_cast<const float4*>(wT + k * 128);
        float4 a0 = ar[(ty * 2) ^ s];
        float4 a1 = ar[(ty * 2 + 1) ^ s];
        float4 b0 = wr[(tx * 2) ^ s];
        float4 b1 = wr[(tx * 2 + 1) ^ s];
        // a pairs along p come free from the vector loads
        unsigned long long ap[4] = {pack2(a0.x, a0.y), pack2(a0.z, a0.w),
                                    pack2(a1.x, a1.y), pack2(a1.z, a1.w)};
        // b broadcast: duplicate each neuron weight into both halves
        unsigned long long bd[8] = {pack2(b0.x, b0.x), pack2(b0.y, b0.y),
                                    pack2(b0.z, b0.z), pack2(b0.w, b0.w),
                                    pack2(b1.x, b1.x), pack2(b1.y, b1.y),
                                    pack2(b1.z, b1.z), pack2(b1.w, b1.w)};
#pragma unroll
        for (int i = 0; i < 4; ++i)
#pragma unroll
            for (int j = 0; j < 8; ++j) ffma2(acc[i][j], ap[i], bd[j]);
    }

    int p0 = ty * 8, n0 = tx * 8;
#pragma unroll
    for (int j = 0; j < 8; ++j) {
        float b = __ldg(bias + n0 + j);
#pragma unroll
        for (int i = 0; i < 4; ++i) {
            float v0, v1;
            unpack2(v0, v1, acc[i][j]);
            v0 += b;
            v1 += b;
            if (SNAKE) {
                float s0 = __sinf(v0);
                float s1 = __sinf(v1);
                v0 = 0.5f * v0 + s0 * s0;
                v1 = 0.5f * v1 + s1 * s1;
            }
            outT[swiz(n0 + j, p0 + 2 * i)]     = v0;
            outT[swiz(n0 + j, p0 + 2 * i + 1)] = v1;
        }
    }
}

__global__ __launch_bounds__(256, 1) void fvsrn_kernel(
    const float* __restrict__ X,
    const float* __restrict__ W0, const float* __restrict__ b0,
    const float* __restrict__ Wh, const float* __restrict__ bh,
    const float* __restrict__ Wout, const float* __restrict__ bout,
    float* __restrict__ out, int n) {
    extern __shared__ float smem[];
    float* bufA   = smem;              // 128x128 swizzled activations (ping)
    float* bufB   = smem + 16384;      // (pong)
    float* wT     = smem + 32768;      // 128x128 swizzled weight tile
    float* wout_s = smem + 49152;      // 128 floats

    const int t  = threadIdx.x;
    const int tx = t & 15;
    const int ty = t >> 4;

    // ---- Stage 0: threads 0..127 build input features; 128..255 stage W0/Wout
    if (t < 128) {
        const int p  = t;
        const int gi = blockIdx.x * 128 + p;
        float x = 0.f, y = 0.f, z = 0.f;
        if (gi < n) {
            x = X[gi * 3 + 0];
            y = X[gi * 3 + 1];
            z = X[gi * 3 + 2];
        }
        // positional encoding: row l*6 + {sin x,y,z, cos x,y,z}
        float f = PI_F;
#pragma unroll
        for (int l = 0; l < 6; ++l) {
            float sx, cx, sy, cy, sz, cz;
            sincosf(x * f, &sx, &cx);
            sincosf(y * f, &sy, &cy);
            sincosf(z * f, &sz, &cz);
            bufA[swiz(l * 6 + 0, p)] = sx;
            bufA[swiz(l * 6 + 1, p)] = sy;
            bufA[swiz(l * 6 + 2, p)] = sz;
            bufA[swiz(l * 6 + 3, p)] = cx;
            bufA[swiz(l * 6 + 4, p)] = cy;
            bufA[swiz(l * 6 + 5, p)] = cz;
            f *= 2.0f;
        }
        // trilinear grid sample, align_corners=True, coords (x,y,z)->(W,H,D)
        float fx = (x + 1.0f) * 0.5f * 63.0f;
        float fy = (y + 1.0f) * 0.5f * 63.0f;
        float fz = (z + 1.0f) * 0.5f * 63.0f;
        int x0 = min(max(__float2int_rd(fx), 0), 63); int x1 = min(x0 + 1, 63);
        int y0 = min(max(__float2int_rd(fy), 0), 63); int y1 = min(y0 + 1, 63);
        int z0 = min(max(__float2int_rd(fz), 0), 63); int z1 = min(z0 + 1, 63);
        float wx1 = fx - (float)x0, wx0 = 1.0f - wx1;
        float wy1 = fy - (float)y0, wy0 = 1.0f - wy1;
        float wz1 = fz - (float)z0, wz0 = 1.0f - wz1;

        float feats[16];
#pragma unroll
        for (int c = 0; c < 16; ++c) feats[c] = 0.0f;
#pragma unroll
        for (int ci = 0; ci < 8; ++ci) {
            int xi = (ci & 1) ? x1 : x0;
            int yi = (ci & 2) ? y1 : y0;
            int zi = (ci & 4) ? z1 : z0;
            float w = ((ci & 4) ? wz1 : wz0) * ((ci & 2) ? wy1 : wy0) *
                      ((ci & 1) ? wx1 : wx0);
            const float4* cp = reinterpret_cast<const float4*>(
                g_gridT + (((zi * 64 + yi) * 64 + xi) << 4));
#pragma unroll
            for (int q = 0; q < 4; ++q) {
                float4 v = __ldg(cp + q);
                feats[4 * q + 0] = fmaf(w, v.x, feats[4 * q + 0]);
                feats[4 * q + 1] = fmaf(w, v.y, feats[4 * q + 1]);
                feats[4 * q + 2] = fmaf(w, v.z, feats[4 * q + 2]);
                feats[4 * q + 3] = fmaf(w, v.w, feats[4 * q + 3]);
            }
        }
#pragma unroll
        for (int c = 0; c < 16; ++c) bufA[swiz(36 + c, p)] = feats[c];
    } else {
        const int tt = t - 128;
        // W0 [128 neurons][52] -> wT logical (row k, col n)
        for (int idx = tt; idx < 128 * 52; idx += 128) {
            int nn = idx / 52;
            int kk = idx - nn * 52;
            wT[swiz(kk, nn)] = W0[idx];
        }
        wout_s[tt] = Wout[tt];
    }
    __syncthreads();

    // ---- Layer 0: [52] -> 128, snake
    gemm_tile<52, true>(bufA, wT, b0, bufB, tx, ty);
    __syncthreads();

    // ---- 3 hidden layers: 128 -> 128, snake (ping-pong bufB/bufA)
    float* pin  = bufB;
    float* pout = bufA;
#pragma unroll 1
    for (int li = 0; li < 3; ++li) {
        const float* W = Wh + li * 16384;  // [n][k] row-major
        // Front-batch all 16 LDG.128 (MLP=16) so one L2 round-trip is exposed,
        // then burst the swizzled STS.
        {
            float4 v[16];
#pragma unroll
            for (int it = 0; it < 16; ++it) {
                int idx = t * 4 + it * 1024;
                v[it] = __ldg(reinterpret_cast<const float4*>(W + idx));
            }
#pragma unroll
            for (int it = 0; it < 16; ++it) {
                int idx = t * 4 + it * 1024;
                int nn = idx >> 7;
                int kk = idx & 127;
                wT[swiz(kk + 0, nn)] = v[it].x;
                wT[swiz(kk + 1, nn)] = v[it].y;
                wT[swiz(kk + 2, nn)] = v[it].z;
                wT[swiz(kk + 3, nn)] = v[it].w;
            }
        }
        __syncthreads();
        gemm_tile<128, true>(pin, wT, bh + li * 128, pout, tx, ty);
        __syncthreads();
        float* tmp = pin; pin = pout; pout = tmp;
    }

    // ---- Output layer: 128 -> 1 (pin holds final activations)
    if (t < 128) {
        const int gi = blockIdx.x * 128 + t;
        if (gi < n) {
            float accum = 0.0f;
#pragma unroll
            for (int k = 0; k < 128; ++k)
                accum = fmaf(pin[swiz(k, t)], wout_s[k], accum);
            out[gi] = accum + __ldg(bout);
        }
    }
}

static const int SMEM_BYTES = (16384 * 3 + 128) * sizeof(float);  // 197120

extern "C" void kernel_launch(void* const* d_in, const int* in_sizes, int n_in,
                              void* d_out, int out_size) {
    const float* x    = (const float*)d_in[0];
    const float* grid = (const float*)d_in[1];
    const float* W0   = (const float*)d_in[2];
    const float* b0   = (const float*)d_in[3];
    const float* Wh   = (const float*)d_in[4];
    const float* bh   = (const float*)d_in[5];
    const float* Wout = (const float*)d_in[6];
    const float* bout = (const float*)d_in[7];
    float* out = (float*)d_out;

    const int n = in_sizes[0] / 3;  // number of points (2^21)

    cudaFuncSetAttribute(fvsrn_kernel,
                         cudaFuncAttributeMaxDynamicSharedMemorySize,
                         SMEM_BYTES);

    // Prolog: [C,D,H,W] -> [D,H,W,C] so gathers are 64B-contiguous per corner.
    grid_transpose_kernel<<<4096, 1024>>>(grid);

    const int blocks = (n + 127) / 128;
    fvsrn_kernel<<<blocks, 256, SMEM_BYTES>>>(x, W0, b0, Wh, bh, Wout, bout,
                                              out, n);
}

// round 8
// speedup vs baseline: 2.7204x; 2.7204x over previous
#include <cuda_runtime.h>
#include <math.h>
#include <stdint.h>

// ===========================================================================
// fVSRN via legacy tensor-core mma.sync (sm_103-safe; tcgen05 is 'a'-gated
// and the harness targets plain sm_103): PE(36)+grid(16) -> [52->128] ->
// 3x[128->128] -> [128->1], snake. bf16 hi/lo 2-term split (3 MMAs per
// logical MMA) gives ~16-bit effective mantissa; fp32 accumulate.
// 128 pts/CTA, 256 thr (8 warps x m16 slab). Activations stay in registers
// across layers (C-fragment == next A-fragment after bf16x2 pack).
// R7 fix: weight row stride 36 -> 68 words (hidden K=128 needs 64 words/row;
// stride 36 aliased adjacent rows). 68 % 32 == 4 keeps B-loads conflict-free.
// ===========================================================================

#define PI_F 3.14159265358979323846f

// Transposed feature grid [D][H][W][C]: each corner gather is 64B contiguous.
__device__ float g_gridT[64 * 64 * 64 * 16];

__global__ void grid_transpose_kernel(const float* __restrict__ g) {
    int i = blockIdx.x * blockDim.x + threadIdx.x;   // 0 .. 2^22-1
    int c = i & 15;
    int s = i >> 4;
    g_gridT[i] = g[c * 262144 + s];
}

// bf16 hi/lo pack: (a, b) -> bf16x2 {lo16=a, hi16=b} + residual bf16x2
__device__ __forceinline__ void pack_hilo(float a, float b,
                                          uint32_t& hi2, uint32_t& lo2) {
    asm("cvt.rn.satfinite.bf16x2.f32 %0, %1, %2;" : "=r"(hi2) : "f"(b), "f"(a));
    float fa = __uint_as_float(hi2 << 16);
    float fb = __uint_as_float(hi2 & 0xffff0000u);
    float la = a - fa;
    float lb = b - fb;
    asm("cvt.rn.satfinite.bf16x2.f32 %0, %1, %2;" : "=r"(lo2) : "f"(lb), "f"(la));
}

__device__ __forceinline__ void mma_bf16(float* c, const uint32_t* a,
                                         uint32_t b0, uint32_t b1) {
    asm volatile(
        "mma.sync.aligned.m16n8k16.row.col.f32.bf16.bf16.f32 "
        "{%0,%1,%2,%3}, {%4,%5,%6,%7}, {%8,%9}, {%0,%1,%2,%3};"
        : "+f"(c[0]), "+f"(c[1]), "+f"(c[2]), "+f"(c[3])
        : "r"(a[0]), "r"(a[1]), "r"(a[2]), "r"(a[3]), "r"(b0), "r"(b1));
}

__device__ __forceinline__ float snake(float v) {
    float s = __sinf(v);
    return 0.5f * v + s * s;
}

// Weight rows: [n][k] as bf16x2 words, stride WSTR words. WSTR=68 >= 64
// (K=128 -> 64 words/row) and 68 % 32 == 4 -> B-fragment LDS pattern is a
// perfect bank permutation (bank = (4g + 8kt + m) mod 32).
static constexpr int WSTR = 68;

// SMEM layout (bytes).
static constexpr int FEAT_OFF  = 0;        // 128 * 68 floats = 34816 B
static constexpr int WHI_OFF   = 34816;    // 128 * 68 words  = 34816 B
static constexpr int WLO_OFF   = 69632;    // 34816 B
static constexpr int BIAS_OFF  = 104448;   // 512 floats = 2048 B
static constexpr int WOUT_OFF  = 106496;   // 128 floats = 512 B
static constexpr int SMEM_TOTAL = 107008;

__global__ __launch_bounds__(256, 1) void fvsrn_kernel(
    const float* __restrict__ X,
    const float* __restrict__ W0, const float* __restrict__ b0,
    const float* __restrict__ Wh, const float* __restrict__ bh,
    const float* __restrict__ Wout, const float* __restrict__ bout,
    float* __restrict__ out, int n) {
    extern __shared__ char smem[];
    float*    feats  = reinterpret_cast<float*>(smem + FEAT_OFF);
    uint32_t* whi    = reinterpret_cast<uint32_t*>(smem + WHI_OFF);
    uint32_t* wlo    = reinterpret_cast<uint32_t*>(smem + WLO_OFF);
    float*    bias_s = reinterpret_cast<float*>(smem + BIAS_OFF);
    float*    wout_s = reinterpret_cast<float*>(smem + WOUT_OFF);

    const int t    = threadIdx.x;
    const int lane = t & 31;
    const int warp = t >> 5;
    const int g    = lane >> 2;     // 0..7: fragment row group / B n-row
    const int m    = lane & 3;      // 0..3: fragment k/n pair selector
    const int p0   = warp * 16 + g; // this thread's first point row

    // ---- Stage 0: t<128 = features + biases; t>=128 = W0 -> SMEM hi/lo ----
    if (t < 128) {
        bias_s[t]       = b0[t];
        bias_s[128 + t] = bh[t];
        bias_s[256 + t] = bh[128 + t];
        bias_s[384 + t] = bh[256 + t];
        wout_s[t]       = Wout[t];

        const int gi = blockIdx.x * 128 + t;
        float x = 0.f, y = 0.f, z = 0.f;
        if (gi < n) {
            x = X[gi * 3 + 0];
            y = X[gi * 3 + 1];
            z = X[gi * 3 + 2];
        }
        float* fp = feats + t * 68;
        // PE: k = l*6 + {sx,sy,sz,cx,cy,cz}
        float fr = PI_F;
#pragma unroll
        for (int l = 0; l < 6; ++l) {
            float sx, cx, sy, cy, sz, cz;
            sincosf(x * fr, &sx, &cx);
            sincosf(y * fr, &sy, &cy);
            sincosf(z * fr, &sz, &cz);
            fp[l * 6 + 0] = sx; fp[l * 6 + 1] = sy; fp[l * 6 + 2] = sz;
            fp[l * 6 + 3] = cx; fp[l * 6 + 4] = cy; fp[l * 6 + 5] = cz;
            fr *= 2.0f;
        }
        // trilinear grid sample (align_corners=True)
        float fx = (x + 1.0f) * 0.5f * 63.0f;
        float fy = (y + 1.0f) * 0.5f * 63.0f;
        float fz = (z + 1.0f) * 0.5f * 63.0f;
        int x0 = min(max(__float2int_rd(fx), 0), 63); int x1 = min(x0 + 1, 63);
        int y0 = min(max(__float2int_rd(fy), 0), 63); int y1 = min(y0 + 1, 63);
        int z0 = min(max(__float2int_rd(fz), 0), 63); int z1 = min(z0 + 1, 63);
        float wx1 = fx - (float)x0, wx0 = 1.0f - wx1;
        float wy1 = fy - (float)y0, wy0 = 1.0f - wy1;
        float wz1 = fz - (float)z0, wz0 = 1.0f - wz1;

        float ft[16];
#pragma unroll
        for (int c = 0; c < 16; ++c) ft[c] = 0.0f;
#pragma unroll
        for (int ci = 0; ci < 8; ++ci) {
            int xi = (ci & 1) ? x1 : x0;
            int yi = (ci & 2) ? y1 : y0;
            int zi = (ci & 4) ? z1 : z0;
            float w = ((ci & 4) ? wz1 : wz0) * ((ci & 2) ? wy1 : wy0) *
                      ((ci & 1) ? wx1 : wx0);
            const float4* cp = reinterpret_cast<const float4*>(
                g_gridT + (((zi * 64 + yi) * 64 + xi) << 4));
#pragma unroll
            for (int q = 0; q < 4; ++q) {
                float4 v = __ldg(cp + q);
                ft[4 * q + 0] = fmaf(w, v.x, ft[4 * q + 0]);
                ft[4 * q + 1] = fmaf(w, v.y, ft[4 * q + 1]);
                ft[4 * q + 2] = fmaf(w, v.z, ft[4 * q + 2]);
                ft[4 * q + 3] = fmaf(w, v.w, ft[4 * q + 3]);
            }
        }
#pragma unroll
        for (int c = 0; c < 16; ++c) fp[36 + c] = ft[c];
#pragma unroll
        for (int k = 52; k < 64; ++k) fp[k] = 0.0f;   // zero-pad K to 64
    } else {
        const int nrow = t - 128;   // one W0 row per thread
        const float* wr = W0 + nrow * 52;
#pragma unroll
        for (int j = 0; j < 32; ++j) {          // word j covers k = 2j, 2j+1
            float a = (2 * j     < 52) ? __ldg(wr + 2 * j)     : 0.0f;
            float b = (2 * j + 1 < 52) ? __ldg(wr + 2 * j + 1) : 0.0f;
            uint32_t hi, lo;
            pack_hilo(a, b, hi, lo);
            whi[nrow * WSTR + j] = hi;
            wlo[nrow * WSTR + j] = lo;
        }
    }
    __syncthreads();

    // ---- Build layer-0 A fragments from feats (4 k-tiles of 16) ----
    uint32_t a0h[4][4], a0l[4][4];
#pragma unroll
    for (int kt = 0; kt < 4; ++kt) {
        const float* r0 = feats + p0 * 68 + kt * 16 + m * 2;
        const float* r1 = feats + (p0 + 8) * 68 + kt * 16 + m * 2;
        pack_hilo(r0[0], r0[1], a0h[kt][0], a0l[kt][0]);
        pack_hilo(r1[0], r1[1], a0h[kt][1], a0l[kt][1]);
        pack_hilo(r0[8], r0[9], a0h[kt][2], a0l[kt][2]);
        pack_hilo(r1[8], r1[9], a0h[kt][3], a0l[kt][3]);
    }

    float C[16][4];
#pragma unroll
    for (int nt = 0; nt < 16; ++nt)
#pragma unroll
        for (int r = 0; r < 4; ++r) C[nt][r] = 0.0f;

    // ---- Layer 0 GEMM: K=64 (4 k-tiles), 3-MMA hi/lo split ----
#pragma unroll
    for (int kt = 0; kt < 4; ++kt) {
#pragma unroll
        for (int nt = 0; nt < 16; ++nt) {
            int wi = (nt * 8 + g) * WSTR + kt * 8 + m;
            uint32_t bh0 = whi[wi], bh1 = whi[wi + 4];
            uint32_t bl0 = wlo[wi], bl1 = wlo[wi + 4];
            mma_bf16(C[nt], a0h[kt], bh0, bh1);
            mma_bf16(C[nt], a0h[kt], bl0, bl1);
            mma_bf16(C[nt], a0l[kt], bh0, bh1);
        }
    }

    // ---- Activate L0 + regen A fragments (register-local) ----
    uint32_t Ahi[8][4], Alo[8][4];
#pragma unroll
    for (int nt = 0; nt < 16; ++nt) {
        int nb = nt * 8 + m * 2;
        float bb0 = bias_s[nb], bb1 = bias_s[nb + 1];
        C[nt][0] = snake(C[nt][0] + bb0);
        C[nt][1] = snake(C[nt][1] + bb1);
        C[nt][2] = snake(C[nt][2] + bb0);
        C[nt][3] = snake(C[nt][3] + bb1);
    }
#pragma unroll
    for (int kt = 0; kt < 8; ++kt) {
        pack_hilo(C[2 * kt][0],     C[2 * kt][1],     Ahi[kt][0], Alo[kt][0]);
        pack_hilo(C[2 * kt][2],     C[2 * kt][3],     Ahi[kt][1], Alo[kt][1]);
        pack_hilo(C[2 * kt + 1][0], C[2 * kt + 1][1], Ahi[kt][2], Alo[kt][2]);
        pack_hilo(C[2 * kt + 1][2], C[2 * kt + 1][3], Ahi[kt][3], Alo[kt][3]);
    }

    // ---- 3 hidden layers ----
#pragma unroll 1
    for (int l = 0; l < 3; ++l) {
        __syncthreads();   // all warps done reading whi/wlo
        {   // stage Wh[l]: 2 threads per n-row, 64 floats each
            const int nrow = t & 127;
            const int h    = t >> 7;
            const float4* w4 = reinterpret_cast<const float4*>(
                Wh + l * 16384 + nrow * 128 + h * 64);
#pragma unroll
            for (int q = 0; q < 16; ++q) {
                float4 w = __ldg(w4 + q);
                uint32_t hi, lo;
                int wi = nrow * WSTR + h * 32 + q * 2;
                pack_hilo(w.x, w.y, hi, lo);
                whi[wi] = hi; wlo[wi] = lo;
                pack_hilo(w.z, w.w, hi, lo);
                whi[wi + 1] = hi; wlo[wi + 1] = lo;
            }
        }
        __syncthreads();

#pragma unroll
        for (int nt = 0; nt < 16; ++nt)
#pragma unroll
            for (int r = 0; r < 4; ++r) C[nt][r] = 0.0f;

#pragma unroll
        for (int kt = 0; kt < 8; ++kt) {
#pragma unroll
            for (int nt = 0; nt < 16; ++nt) {
                int wi = (nt * 8 + g) * WSTR + kt * 8 + m;
                uint32_t bh0 = whi[wi], bh1 = whi[wi + 4];
                uint32_t bl0 = wlo[wi], bl1 = wlo[wi + 4];
                mma_bf16(C[nt], Ahi[kt], bh0, bh1);
                mma_bf16(C[nt], Ahi[kt], bl0, bl1);
                mma_bf16(C[nt], Alo[kt], bh0, bh1);
            }
        }

        // activate + regen (regen harmless on last iteration)
        const float* bl = bias_s + 128 + l * 128;
#pragma unroll
        for (int nt = 0; nt < 16; ++nt) {
            int nb = nt * 8 + m * 2;
            float bb0 = bl[nb], bb1 = bl[nb + 1];
            C[nt][0] = snake(C[nt][0] + bb0);
            C[nt][1] = snake(C[nt][1] + bb1);
            C[nt][2] = snake(C[nt][2] + bb0);
            C[nt][3] = snake(C[nt][3] + bb1);
        }
#pragma unroll
        for (int kt = 0; kt < 8; ++kt) {
            pack_hilo(C[2 * kt][0],     C[2 * kt][1],     Ahi[kt][0], Alo[kt][0]);
            pack_hilo(C[2 * kt][2],     C[2 * kt][3],     Ahi[kt][1], Alo[kt][1]);
            pack_hilo(C[2 * kt + 1][0], C[2 * kt + 1][1], Ahi[kt][2], Alo[kt][2]);
            pack_hilo(C[2 * kt + 1][2], C[2 * kt + 1][3], Ahi[kt][3], Alo[kt][3]);
        }
    }

    // ---- Output layer: dot with wout, quad-reduce, store ----
    float pr0 = 0.0f, pr1 = 0.0f;
#pragma unroll
    for (int nt = 0; nt < 16; ++nt) {
        int nb = nt * 8 + m * 2;
        float w0v = wout_s[nb], w1v = wout_s[nb + 1];
        pr0 = fmaf(C[nt][0], w0v, fmaf(C[nt][1], w1v, pr0));
        pr1 = fmaf(C[nt][2], w0v, fmaf(C[nt][3], w1v, pr1));
    }
    pr0 += __shfl_xor_sync(0xFFFFFFFFu, pr0, 1);
    pr0 += __shfl_xor_sync(0xFFFFFFFFu, pr0, 2);
    pr1 += __shfl_xor_sync(0xFFFFFFFFu, pr1, 1);
    pr1 += __shfl_xor_sync(0xFFFFFFFFu, pr1, 2);
    if (m == 0) {
        float bo = __ldg(bout);
        int gi = blockIdx.x * 128 + p0;
        if (gi < n)     out[gi]     = pr0 + bo;
        if (gi + 8 < n) out[gi + 8] = pr1 + bo;
    }
}

extern "C" void kernel_launch(void* const* d_in, const int* in_sizes, int n_in,
                              void* d_out, int out_size) {
    const float* x    = (const float*)d_in[0];
    const float* grid = (const float*)d_in[1];
    const float* W0   = (const float*)d_in[2];
    const float* b0   = (const float*)d_in[3];
    const float* Wh   = (const float*)d_in[4];
    const float* bh   = (const float*)d_in[5];
    const float* Wout = (const float*)d_in[6];
    const float* bout = (const float*)d_in[7];
    float* out = (float*)d_out;

    const int n = in_sizes[0] / 3;

    cudaFuncSetAttribute(fvsrn_kernel,
                         cudaFuncAttributeMaxDynamicSharedMemorySize,
                         SMEM_TOTAL);

    grid_transpose_kernel<<<4096, 1024>>>(grid);

    const int blocks = (n + 127) / 128;
    fvsrn_kernel<<<blocks, 256, SMEM_TOTAL>>>(x, W0, b0, Wh, bh, Wout, bout,
                                              out, n);
}

// round 10
// speedup vs baseline: 3.6608x; 1.3457x over previous
#include <cuda_runtime.h>
#include <math.h>
#include <stdint.h>

// ===========================================================================
// fVSRN via mma.sync m16n8k16 bf16 (sm_103-safe), hi/lo 2-term split
// (3 MMAs / logical MMA), fp32 accumulate. Register-resident activation
// relay across layers. R9: weights pre-packed to global fragment-quads by a
// prolog kernel; cp.async double-buffered prefetch; LDS.128 B-fragment loads.
// ===========================================================================

#define PI_F 3.14159265358979323846f

__device__ float    g_gridT[64 * 64 * 64 * 16];      // [D][H][W][C]
__device__ uint32_t g_wpack[4 * 128 * 144];          // 4 layers x 128 rows x 144 words

__global__ void grid_transpose_kernel(const float* __restrict__ g) {
    int i = blockIdx.x * blockDim.x + threadIdx.x;
    int c = i & 15;
    int s = i >> 4;
    g_gridT[i] = g[c * 262144 + s];
}

// bf16 hi/lo pack: (a, b) -> bf16x2 {lo16=a, hi16=b} + residual bf16x2
__device__ __forceinline__ void pack_hilo(float a, float b,
                                          uint32_t& hi2, uint32_t& lo2) {
    asm("cvt.rn.satfinite.bf16x2.f32 %0, %1, %2;" : "=r"(hi2) : "f"(b), "f"(a));
    float fa = __uint_as_float(hi2 << 16);
    float fb = __uint_as_float(hi2 & 0xffff0000u);
    float la = a - fa;
    float lb = b - fb;
    asm("cvt.rn.satfinite.bf16x2.f32 %0, %1, %2;" : "=r"(lo2) : "f"(lb), "f"(la));
}

// Prolog: weights -> fragment-quad layout. quad(l,r,kt,m) = {b0h,b1h,b0l,b1l}
// b0 covers k = 16kt+2m..+1, b1 covers k = 16kt+2m+8..+1 (col-major B frag).
__global__ void pack_weights_kernel(const float* __restrict__ W0,
                                    const float* __restrict__ Wh) {
    int q  = blockIdx.x * blockDim.x + threadIdx.x;   // 0..16383
    int m  = q & 3;
    int kt = (q >> 2) & 7;
    int r  = (q >> 5) & 127;
    int l  = q >> 12;
    int ka = kt * 16 + m * 2;
    int kb = ka + 8;
    float wa0, wa1, wb0, wb1;
    if (l == 0) {
        const float* w = W0 + r * 52;
        wa0 = (ka     < 52) ? w[ka]     : 0.0f;
        wa1 = (ka + 1 < 52) ? w[ka + 1] : 0.0f;
        wb0 = (kb     < 52) ? w[kb]     : 0.0f;
        wb1 = (kb + 1 < 52) ? w[kb + 1] : 0.0f;
    } else {
        const float* w = Wh + (l - 1) * 16384 + r * 128;
        wa0 = w[ka]; wa1 = w[ka + 1]; wb0 = w[kb]; wb1 = w[kb + 1];
    }
    uint32_t h0, l0, h1, l1;
    pack_hilo(wa0, wa1, h0, l0);
    pack_hilo(wb0, wb1, h1, l1);
    uint32_t* dst = g_wpack + (l * 128 + r) * 144 + kt * 16 + m * 4;
    dst[0] = h0; dst[1] = h1; dst[2] = l0; dst[3] = l1;
}

__device__ __forceinline__ void mma_bf16(float* c, const uint32_t* a,
                                         uint32_t b0, uint32_t b1) {
    asm volatile(
        "mma.sync.aligned.m16n8k16.row.col.f32.bf16.bf16.f32 "
        "{%0,%1,%2,%3}, {%4,%5,%6,%7}, {%8,%9}, {%0,%1,%2,%3};"
        : "+f"(c[0]), "+f"(c[1]), "+f"(c[2]), "+f"(c[3])
        : "r"(a[0]), "r"(a[1]), "r"(a[2]), "r"(a[3]), "r"(b0), "r"(b1));
}

__device__ __forceinline__ float snake(float v) {
    float s = __sinf(v);
    return 0.5f * v + s * s;
}

__device__ __forceinline__ uint32_t smem_u32_of(const void* p) {
    uint32_t a;
    asm("{ .reg .u64 t; cvta.to.shared.u64 t, %1; cvt.u32.u64 %0, t; }"
        : "=r"(a) : "l"(p));
    return a;
}

#define CP_ASYNC_16(dst_u32, src) \
    asm volatile("cp.async.cg.shared.global [%0], [%1], 16;" \
        :: "r"(dst_u32), "l"(src))
#define CP_COMMIT() asm volatile("cp.async.commit_group;" ::: "memory")
#define CP_WAIT_1() asm volatile("cp.async.wait_group 1;" ::: "memory")
#define CP_WAIT_0() asm volatile("cp.async.wait_group 0;" ::: "memory")

// Weight buffer: [128 rows][144 words], stride 144 (144 mod 32 == 16 ->
// LDS.128 phases hit disjoint bank quartets; conflict-free).
static constexpr int LAYER_WORDS = 128 * 144;            // 18432 words
static constexpr int LAYER_BYTES = LAYER_WORDS * 4;      // 73728 B

// SMEM layout (bytes)
static constexpr int FEAT_OFF  = 0;        // 128 * 68 floats = 34816 B
static constexpr int WBUF_OFF  = 34816;    // 2 x 73728 = 147456 B
static constexpr int BIAS_OFF  = 182272;   // 512 floats
static constexpr int WOUT_OFF  = 184320;   // 128 floats
static constexpr int SMEM_TOTAL = 184832;

__device__ __forceinline__ void prefetch_layer(uint32_t dst_u32,
                                               const uint32_t* gsrc, int t) {
#pragma unroll
    for (int i = 0; i < 18; ++i) {
        int c = i * 256 + t;                    // 4608 16B chunks total
        CP_ASYNC_16(dst_u32 + c * 16,
                    reinterpret_cast<const char*>(gsrc) + c * 16);
    }
    CP_COMMIT();
}

__global__ __launch_bounds__(256, 1) void fvsrn_kernel(
    const float* __restrict__ X,
    const float* __restrict__ b0, const float* __restrict__ bh,
    const float* __restrict__ Wout, const float* __restrict__ bout,
    float* __restrict__ out, int n) {
    extern __shared__ char smem[];
    float*    feats  = reinterpret_cast<float*>(smem + FEAT_OFF);
    uint32_t* wbuf   = reinterpret_cast<uint32_t*>(smem + WBUF_OFF);
    float*    bias_s = reinterpret_cast<float*>(smem + BIAS_OFF);
    float*    wout_s = reinterpret_cast<float*>(smem + WOUT_OFF);
    const uint32_t wbuf_u32 = smem_u32_of(wbuf);

    const int t    = threadIdx.x;
    const int lane = t & 31;
    const int warp = t >> 5;
    const int g    = lane >> 2;
    const int m    = lane & 3;
    const int p0   = warp * 16 + g;

    // ---- Kick off weight prefetch for layers 0 and 1 ----
    prefetch_layer(wbuf_u32, g_wpack, t);                              // g0 -> buf0
    prefetch_layer(wbuf_u32 + LAYER_BYTES, g_wpack + LAYER_WORDS, t);  // g1 -> buf1

    // ---- Stage 0: t<128 computes features + biases ----
    if (t < 128) {
        bias_s[t]       = b0[t];
        bias_s[128 + t] = bh[t];
        bias_s[256 + t] = bh[128 + t];
        bias_s[384 + t] = bh[256 + t];
        wout_s[t]       = Wout[t];

        const int gi = blockIdx.x * 128 + t;
        float x = 0.f, y = 0.f, z = 0.f;
        if (gi < n) {
            x = X[gi * 3 + 0];
            y = X[gi * 3 + 1];
            z = X[gi * 3 + 2];
        }
        float* fp = feats + t * 68;
        float fr = PI_F;
#pragma unroll
        for (int l = 0; l < 6; ++l) {
            float sx, cx, sy, cy, sz, cz;
            sincosf(x * fr, &sx, &cx);
            sincosf(y * fr, &sy, &cy);
            sincosf(z * fr, &sz, &cz);
            fp[l * 6 + 0] = sx; fp[l * 6 + 1] = sy; fp[l * 6 + 2] = sz;
            fp[l * 6 + 3] = cx; fp[l * 6 + 4] = cy; fp[l * 6 + 5] = cz;
            fr *= 2.0f;
        }
        float fx = (x + 1.0f) * 0.5f * 63.0f;
        float fy = (y + 1.0f) * 0.5f * 63.0f;
        float fz = (z + 1.0f) * 0.5f * 63.0f;
        int x0 = min(max(__float2int_rd(fx), 0), 63); int x1 = min(x0 + 1, 63);
        int y0 = min(max(__float2int_rd(fy), 0), 63); int y1 = min(y0 + 1, 63);
        int z0 = min(max(__float2int_rd(fz), 0), 63); int z1 = min(z0 + 1, 63);
        float wx1 = fx - (float)x0, wx0 = 1.0f - wx1;
        float wy1 = fy - (float)y0, wy0 = 1.0f - wy1;
        float wz1 = fz - (float)z0, wz0 = 1.0f - wz1;

        float ft[16];
#pragma unroll
        for (int c = 0; c < 16; ++c) ft[c] = 0.0f;
#pragma unroll
        for (int ci = 0; ci < 8; ++ci) {
            int xi = (ci & 1) ? x1 : x0;
            int yi = (ci & 2) ? y1 : y0;
            int zi = (ci & 4) ? z1 : z0;
            float w = ((ci & 4) ? wz1 : wz0) * ((ci & 2) ? wy1 : wy0) *
                      ((ci & 1) ? wx1 : wx0);
            const float4* cp = reinterpret_cast<const float4*>(
                g_gridT + (((zi * 64 + yi) * 64 + xi) << 4));
#pragma unroll
            for (int qq = 0; qq < 4; ++qq) {
                float4 v = __ldg(cp + qq);
                ft[4 * qq + 0] = fmaf(w, v.x, ft[4 * qq + 0]);
                ft[4 * qq + 1] = fmaf(w, v.y, ft[4 * qq + 1]);
                ft[4 * qq + 2] = fmaf(w, v.z, ft[4 * qq + 2]);
                ft[4 * qq + 3] = fmaf(w, v.w, ft[4 * qq + 3]);
            }
        }
#pragma unroll
        for (int c = 0; c < 16; ++c) fp[36 + c] = ft[c];
#pragma unroll
        for (int k = 52; k < 64; ++k) fp[k] = 0.0f;
    }
    CP_WAIT_1();          // layer-0 weights landed
    __syncthreads();

    // ---- Build layer-0 A fragments (4 k-tiles of 16) ----
    uint32_t a0h[4][4], a0l[4][4];
#pragma unroll
    for (int kt = 0; kt < 4; ++kt) {
        const float* r0 = feats + p0 * 68 + kt * 16 + m * 2;
        const float* r1 = feats + (p0 + 8) * 68 + kt * 16 + m * 2;
        pack_hilo(r0[0], r0[1], a0h[kt][0], a0l[kt][0]);
        pack_hilo(r1[0], r1[1], a0h[kt][1], a0l[kt][1]);
        pack_hilo(r0[8], r0[9], a0h[kt][2], a0l[kt][2]);
        pack_hilo(r1[8], r1[9], a0h[kt][3], a0l[kt][3]);
    }

    float C[16][4];
#pragma unroll
    for (int nt = 0; nt < 16; ++nt)
#pragma unroll
        for (int r = 0; r < 4; ++r) C[nt][r] = 0.0f;

    // ---- Layer 0 GEMM: K=64, 3-MMA hi/lo split, quad LDS.128 loads ----
#pragma unroll
    for (int kt = 0; kt < 4; ++kt) {
#pragma unroll
        for (int nt = 0; nt < 16; ++nt) {
            const uint4 q = *reinterpret_cast<const uint4*>(
                wbuf + ((nt * 8 + g) * 144 + kt * 16 + m * 4));
            mma_bf16(C[nt], a0h[kt], q.x, q.y);
            mma_bf16(C[nt], a0h[kt], q.z, q.w);
            mma_bf16(C[nt], a0l[kt], q.x, q.y);
        }
    }

    // ---- Activate L0 + regen A fragments ----
    uint32_t Ahi[8][4], Alo[8][4];
#pragma unroll
    for (int nt = 0; nt < 16; ++nt) {
        int nb = nt * 8 + m * 2;
        float bb0 = bias_s[nb], bb1 = bias_s[nb + 1];
        C[nt][0] = snake(C[nt][0] + bb0);
        C[nt][1] = snake(C[nt][1] + bb1);
        C[nt][2] = snake(C[nt][2] + bb0);
        C[nt][3] = snake(C[nt][3] + bb1);
    }
#pragma unroll
    for (int kt = 0; kt < 8; ++kt) {
        pack_hilo(C[2 * kt][0],     C[2 * kt][1],     Ahi[kt][0], Alo[kt][0]);
        pack_hilo(C[2 * kt][2],     C[2 * kt][3],     Ahi[kt][1], Alo[kt][1]);
        pack_hilo(C[2 * kt + 1][0], C[2 * kt + 1][1], Ahi[kt][2], Alo[kt][2]);
        pack_hilo(C[2 * kt + 1][2], C[2 * kt + 1][3], Ahi[kt][3], Alo[kt][3]);
    }

    // ---- 3 hidden layers: buf = l%2, prefetch l+1 into the freed buffer ----
#pragma unroll 1
    for (int l = 1; l <= 3; ++l) {
        __syncthreads();   // all warps done reading buf[(l+1)%2]
        if (l <= 2)
            prefetch_layer(wbuf_u32 + ((l + 1) & 1) * LAYER_BYTES,
                           g_wpack + (l + 1) * LAYER_WORDS, t);
        if (l < 3) { CP_WAIT_1(); } else { CP_WAIT_0(); }
        __syncthreads();

        const uint32_t* wb = wbuf + (l & 1) * LAYER_WORDS;

#pragma unroll
        for (int nt = 0; nt < 16; ++nt)
#pragma unroll
            for (int r = 0; r < 4; ++r) C[nt][r] = 0.0f;

#pragma unroll
        for (int kt = 0; kt < 8; ++kt) {
#pragma unroll
            for (int nt = 0; nt < 16; ++nt) {
                const uint4 q = *reinterpret_cast<const uint4*>(
                    wb + ((nt * 8 + g) * 144 + kt * 16 + m * 4));
                mma_bf16(C[nt], Ahi[kt], q.x, q.y);
                mma_bf16(C[nt], Ahi[kt], q.z, q.w);
                mma_bf16(C[nt], Alo[kt], q.x, q.y);
            }
        }

        const float* bl = bias_s + l * 128;
#pragma unroll
        for (int nt = 0; nt < 16; ++nt) {
            int nb = nt * 8 + m * 2;
            float bb0 = bl[nb], bb1 = bl[nb + 1];
            C[nt][0] = snake(C[nt][0] + bb0);
            C[nt][1] = snake(C[nt][1] + bb1);
            C[nt][2] = snake(C[nt][2] + bb0);
            C[nt][3] = snake(C[nt][3] + bb1);
        }
#pragma unroll
        for (int kt = 0; kt < 8; ++kt) {
            pack_hilo(C[2 * kt][0],     C[2 * kt][1],     Ahi[kt][0], Alo[kt][0]);
            pack_hilo(C[2 * kt][2],     C[2 * kt][3],     Ahi[kt][1], Alo[kt][1]);
            pack_hilo(C[2 * kt + 1][0], C[2 * kt + 1][1], Ahi[kt][2], Alo[kt][2]);
            pack_hilo(C[2 * kt + 1][2], C[2 * kt + 1][3], Ahi[kt][3], Alo[kt][3]);
        }
    }

    // ---- Output layer: dot with wout, quad-reduce, store ----
    float pr0 = 0.0f, pr1 = 0.0f;
#pragma unroll
    for (int nt = 0; nt < 16; ++nt) {
        int nb = nt * 8 + m * 2;
        float w0v = wout_s[nb], w1v = wout_s[nb + 1];
        pr0 = fmaf(C[nt][0], w0v, fmaf(C[nt][1], w1v, pr0));
        pr1 = fmaf(C[nt][2], w0v, fmaf(C[nt][3], w1v, pr1));
    }
    pr0 += __shfl_xor_sync(0xFFFFFFFFu, pr0, 1);
    pr0 += __shfl_xor_sync(0xFFFFFFFFu, pr0, 2);
    pr1 += __shfl_xor_sync(0xFFFFFFFFu, pr1, 1);
    pr1 += __shfl_xor_sync(0xFFFFFFFFu, pr1, 2);
    if (m == 0) {
        float bo = __ldg(bout);
        int gi = blockIdx.x * 128 + p0;
        if (gi < n)     out[gi]     = pr0 + bo;
        if (gi + 8 < n) out[gi + 8] = pr1 + bo;
    }
}

extern "C" void kernel_launch(void* const* d_in, const int* in_sizes, int n_in,
                              void* d_out, int out_size) {
    const float* x    = (const float*)d_in[0];
    const float* grid = (const float*)d_in[1];
    const float* W0   = (const float*)d_in[2];
    const float* b0   = (const float*)d_in[3];
    const float* Wh   = (const float*)d_in[4];
    const float* bh   = (const float*)d_in[5];
    const float* Wout = (const float*)d_in[6];
    const float* bout = (const float*)d_in[7];
    float* out = (float*)d_out;

    const int n = in_sizes[0] / 3;

    cudaFuncSetAttribute(fvsrn_kernel,
                         cudaFuncAttributeMaxDynamicSharedMemorySize,
                         SMEM_TOTAL);

    grid_transpose_kernel<<<4096, 1024>>>(grid);
    pack_weights_kernel<<<64, 256>>>(W0, Wh);

    const int blocks = (n + 127) / 128;
    fvsrn_kernel<<<blocks, 256, SMEM_TOTAL>>>(x, b0, bh, Wout, bout, out, n);
}